// round 3
// baseline (speedup 1.0000x reference)
#include <cuda_runtime.h>

// ---------------------------------------------------------------------------
// RModel_29257317221019: fused cos-MLP deform (3->32->32->32->3) + trilinear
// sample from 256^3 volume. 2 points per thread via packed f32x2 (FFMA2).
// Inputs (metadata order): x(64*32*32*32*4), W1(3,32), b1(32), W2(32,32),
// b2(32), W3(32,32), b3(32), Wf(32,3), bf(3), vol(256,256,256,1).
// Output: (64,32,32,32,1) float32.
// ---------------------------------------------------------------------------

typedef unsigned long long u64;

__device__ __forceinline__ u64 pk2(float lo, float hi) {
    u64 r; asm("mov.b64 %0, {%1, %2};" : "=l"(r) : "f"(lo), "f"(hi)); return r;
}
__device__ __forceinline__ void upk2(u64 v, float& lo, float& hi) {
    asm("mov.b64 {%0, %1}, %2;" : "=f"(lo), "=f"(hi) : "l"(v));
}
__device__ __forceinline__ u64 ffma2(u64 a, u64 b, u64 c) {
    u64 r; asm("fma.rn.f32x2 %0, %1, %2, %3;" : "=l"(r) : "l"(a), "l"(b), "l"(c)); return r;
}
__device__ __forceinline__ u64 cos2(u64 v) {
    float lo, hi; upk2(v, lo, hi);
    return pk2(__cosf(lo), __cosf(hi));
}

// Shared-memory layout (packed duplicated weights, 8B each)
#define OFF_W1 0       // 96   (c*32+d)
#define OFF_B1 96      // 32
#define OFF_W2 128     // 1024 (k*32+d)
#define OFF_B2 1152    // 32
#define OFF_W3 1184    // 1024 (k*32+d)
#define OFF_B3 2208    // 32
#define OFF_WF 2240    // 96   (k*3+j)
#define OFF_BF 2336    // 3
#define SW_TOTAL 2339

__global__ __launch_bounds__(256, 1)
void deform_sample_kernel(
    const float* __restrict__ x,
    const float* __restrict__ W1, const float* __restrict__ b1,
    const float* __restrict__ W2, const float* __restrict__ b2,
    const float* __restrict__ W3, const float* __restrict__ b3,
    const float* __restrict__ Wf, const float* __restrict__ bf,
    const float* __restrict__ vol,
    float* __restrict__ out,
    int npairs)
{
    __shared__ u64 sw[SW_TOTAL];

    // Cooperative weight fill (duplicated into both f32x2 halves)
    {
        int tid = threadIdx.x;
        for (int i = tid; i < 96;   i += 256) { float v = W1[i]; sw[OFF_W1 + i] = pk2(v, v); }
        for (int i = tid; i < 32;   i += 256) { float v = b1[i]; sw[OFF_B1 + i] = pk2(v, v); }
        for (int i = tid; i < 1024; i += 256) { float v = W2[i]; sw[OFF_W2 + i] = pk2(v, v); }
        for (int i = tid; i < 32;   i += 256) { float v = b2[i]; sw[OFF_B2 + i] = pk2(v, v); }
        for (int i = tid; i < 1024; i += 256) { float v = W3[i]; sw[OFF_W3 + i] = pk2(v, v); }
        for (int i = tid; i < 32;   i += 256) { float v = b3[i]; sw[OFF_B3 + i] = pk2(v, v); }
        for (int i = tid; i < 96;   i += 256) { float v = Wf[i]; sw[OFF_WF + i] = pk2(v, v); }
        for (int i = tid; i < 3;    i += 256) { float v = bf[i]; sw[OFF_BF + i] = pk2(v, v); }
    }
    __syncthreads();

    int t = blockIdx.x * blockDim.x + threadIdx.x;
    if (t >= npairs) return;

    // Load two consecutive points (x layout: 4 floats per point, coords in [0:3])
    const float4* x4 = reinterpret_cast<const float4*>(x);
    float4 A = x4[2 * t + 0];
    float4 B = x4[2 * t + 1];
    u64 c0 = pk2(A.x, B.x);
    u64 c1 = pk2(A.y, B.y);
    u64 c2 = pk2(A.z, B.z);

    u64 h[32];
    u64 g[32];

    // Layer 1: h = cos(c @ W1 + b1)
#pragma unroll
    for (int d = 0; d < 32; d++) {
        u64 acc = sw[OFF_B1 + d];
        acc = ffma2(c0, sw[OFF_W1 + 0 * 32 + d], acc);
        acc = ffma2(c1, sw[OFF_W1 + 1 * 32 + d], acc);
        acc = ffma2(c2, sw[OFF_W1 + 2 * 32 + d], acc);
        h[d] = cos2(acc);
    }

    // Layer 2: g = cos(h @ W2 + b2)
#pragma unroll
    for (int d = 0; d < 32; d++) {
        u64 acc = sw[OFF_B2 + d];
#pragma unroll
        for (int k = 0; k < 32; k++) {
            acc = ffma2(h[k], sw[OFF_W2 + k * 32 + d], acc);
        }
        g[d] = cos2(acc);
    }

    // Layer 3: h = cos(g @ W3 + b3)
#pragma unroll
    for (int d = 0; d < 32; d++) {
        u64 acc = sw[OFF_B3 + d];
#pragma unroll
        for (int k = 0; k < 32; k++) {
            acc = ffma2(g[k], sw[OFF_W3 + k * 32 + d], acc);
        }
        h[d] = cos2(acc);
    }

    // Final layer + deform: coord = c + 5 * (h @ Wf + bf)
    const u64 FIVE = pk2(5.0f, 5.0f);
    u64 pc[3];
    u64 cin[3] = { c0, c1, c2 };
#pragma unroll
    for (int j = 0; j < 3; j++) {
        u64 acc = sw[OFF_BF + j];
#pragma unroll
        for (int k = 0; k < 32; k++) {
            acc = ffma2(h[k], sw[OFF_WF + k * 3 + j], acc);
        }
        pc[j] = ffma2(FIVE, acc, cin[j]);
    }

    // Trilinear sample for the two points (scalar)
    float px[2], py[2], pz[2];
    upk2(pc[0], px[0], px[1]);
    upk2(pc[1], py[0], py[1]);
    upk2(pc[2], pz[0], pz[1]);

    float res[2];
#pragma unroll
    for (int s = 0; s < 2; s++) {
        float cx = fminf(fmaxf(px[s], 0.0f), 255.0f);
        float cy = fminf(fmaxf(py[s], 0.0f), 255.0f);
        float cz = fminf(fmaxf(pz[s], 0.0f), 255.0f);

        float fx0 = floorf(cx), fy0 = floorf(cy), fz0 = floorf(cz);
        int ix0 = (int)fx0, iy0 = (int)fy0, iz0 = (int)fz0;
        int ix1 = min(ix0 + 1, 255);
        int iy1 = min(iy0 + 1, 255);
        int iz1 = min(iz0 + 1, 255);

        float fx = cx - fx0, fy = cy - fy0, fz = cz - fz0;
        float gx = 1.0f - fx, gy = 1.0f - fy, gz = 1.0f - fz;

        int X0 = ix0 << 16, X1 = ix1 << 16;
        int Y0 = iy0 << 8,  Y1 = iy1 << 8;

        float v000 = __ldg(vol + (X0 + Y0 + iz0));
        float v100 = __ldg(vol + (X1 + Y0 + iz0));
        float v010 = __ldg(vol + (X0 + Y1 + iz0));
        float v001 = __ldg(vol + (X0 + Y0 + iz1));
        float v110 = __ldg(vol + (X1 + Y1 + iz0));
        float v101 = __ldg(vol + (X1 + Y0 + iz1));
        float v011 = __ldg(vol + (X0 + Y1 + iz1));
        float v111 = __ldg(vol + (X1 + Y1 + iz1));

        float r;
        r  = v000 * (gx * gy * gz);
        r += v100 * (fx * gy * gz);
        r += v010 * (gx * fy * gz);
        r += v001 * (gx * gy * fz);
        r += v110 * (fx * fy * gz);
        r += v101 * (fx * gy * fz);
        r += v011 * (gx * fy * fz);
        r += v111 * (fx * fy * fz);
        res[s] = r;
    }

    float2 o;
    o.x = res[0];
    o.y = res[1];
    reinterpret_cast<float2*>(out)[t] = o;
}

extern "C" void kernel_launch(void* const* d_in, const int* in_sizes, int n_in,
                              void* d_out, int out_size) {
    const float* x   = (const float*)d_in[0];
    const float* W1  = (const float*)d_in[1];
    const float* b1  = (const float*)d_in[2];
    const float* W2  = (const float*)d_in[3];
    const float* b2  = (const float*)d_in[4];
    const float* W3  = (const float*)d_in[5];
    const float* b3  = (const float*)d_in[6];
    const float* Wf  = (const float*)d_in[7];
    const float* bf  = (const float*)d_in[8];
    const float* vol = (const float*)d_in[9];
    float* out = (float*)d_out;

    int npts = out_size;           // 2,097,152 points
    int npairs = npts / 2;         // 2 points per thread
    int block = 256;
    int grid = (npairs + block - 1) / block;

    deform_sample_kernel<<<grid, block>>>(x, W1, b1, W2, b2, W3, b3, Wf, bf,
                                          vol, out, npairs);
}